// round 11
// baseline (speedup 1.0000x reference)
#include <cuda_runtime.h>
#include <math.h>

#define BATCH   128
#define NTOK    196
#define HEADS   16
#define HD      32
#define CDIM    512
#define NQKV    1536
#define MROWS   (BATCH * NTOK)          // 25088
#define BH_ELEM (NTOK * HD)             // 6272 floats per (b,h) tensor slice

// -------------------- scratch (device globals; no allocations) --------------------
__device__ __align__(128) float g_q [BATCH * HEADS * NTOK * HD];   // scaled Q, [b,h,n,hd]
__device__ __align__(128) float g_k [BATCH * HEADS * NTOK * HD];
__device__ __align__(128) float g_v [BATCH * HEADS * NTOK * HD];
__device__ __align__(128) float g_ao[MROWS * CDIM];                // attention output, [b*n, h*hd]

// =====================================================================================
// Kernel 1: QKV GEMM.  C[25088,1536] = X[25088,512] @ W[512,1536]
// BM=BN=128, BK=8, 256 threads, 8x8 register tile.  Epilogue scatters to q/k/v
// in [b,h,n,hd] layout, scaling Q by 32^-0.5.
// =====================================================================================
__global__ __launch_bounds__(256)
void qkv_gemm_kernel(const float* __restrict__ X, const float* __restrict__ W)
{
    __shared__ float As[8][128];   // transposed: As[k][m]
    __shared__ float Bs[8][128];

    const int tid = threadIdx.x;
    const int bm = blockIdx.y, bn = blockIdx.x;

    const int arow = tid >> 1;            // 0..127
    const int acol = (tid & 1) << 2;      // 0 or 4
    const int brow = tid >> 5;            // 0..7
    const int bcol = (tid & 31) << 2;     // 0..124

    const float* Ap = X + (size_t)(bm * 128 + arow) * CDIM + acol;
    const float* Bp = W + (size_t)brow * NQKV + bn * 128 + bcol;

    float4 aR = *(const float4*)Ap;
    float4 bR = *(const float4*)Bp;

    float acc[8][8] = {};
    const int tx = tid & 15, ty = tid >> 4;

    for (int kt = 0; kt < CDIM / 8; ++kt) {
        As[acol + 0][arow] = aR.x;
        As[acol + 1][arow] = aR.y;
        As[acol + 2][arow] = aR.z;
        As[acol + 3][arow] = aR.w;
        *(float4*)&Bs[brow][bcol] = bR;
        __syncthreads();

        if (kt < CDIM / 8 - 1) {
            aR = *(const float4*)(Ap + (kt + 1) * 8);
            bR = *(const float4*)(Bp + (size_t)(kt + 1) * 8 * NQKV);
        }

        #pragma unroll
        for (int kk = 0; kk < 8; ++kk) {
            float a[8], b[8];
            *(float4*)&a[0] = *(const float4*)&As[kk][ty * 8];
            *(float4*)&a[4] = *(const float4*)&As[kk][ty * 8 + 4];
            *(float4*)&b[0] = *(const float4*)&Bs[kk][tx * 8];
            *(float4*)&b[4] = *(const float4*)&Bs[kk][tx * 8 + 4];
            #pragma unroll
            for (int i = 0; i < 8; ++i)
                #pragma unroll
                for (int j = 0; j < 8; ++j)
                    acc[i][j] += a[i] * b[j];
        }
        __syncthreads();
    }

    const float SCALE = 0.17677669529663687f;   // (512/16)^-0.5
    #pragma unroll
    for (int i = 0; i < 8; ++i) {
        int row = bm * 128 + ty * 8 + i;
        int b   = row / NTOK;
        int t   = row - b * NTOK;
        #pragma unroll
        for (int j = 0; j < 8; ++j) {
            int col = bn * 128 + tx * 8 + j;
            int s   = col >> 9;           // 0=q, 1=k, 2=v
            int hh  = (col >> 5) & 15;
            int d   = col & 31;
            size_t idx = ((size_t)(b * HEADS + hh) * NTOK + t) * HD + d;
            float v = acc[i][j];
            if      (s == 0) g_q[idx] = v * SCALE;
            else if (s == 1) g_k[idx] = v;
            else             g_v[idx] = v;
        }
    }
}

// =====================================================================================
// Kernel 2: fused attention per (b,h).  grid = 2048, 256 threads (8 warps).
// smem: Kt[32][196] (transposed K), Vs[196][32], Qs[196][32], tab[729] (bias column
// for head h), Pb[8][784] per-warp softmax probs interleaved x4 queries.
// Each warp processes groups of 4 queries (49 groups round-robin over 8 warps).
// =====================================================================================
__global__ __launch_bounds__(256)
void attn_kernel(const float* __restrict__ bias_table)
{
    extern __shared__ float sm[];
    float* Kt  = sm;                 // 6272
    float* Vs  = sm + 6272;          // 6272
    float* Qs  = sm + 12544;         // 6272
    float* tab = sm + 18816;         // 729 (+7 pad)
    float* Pb  = sm + 19552;         // 8 * 784

    const int tid = threadIdx.x;
    const int bh  = blockIdx.x;
    const int b   = bh >> 4;
    const int h   = bh & 15;
    const size_t base = (size_t)bh * BH_ELEM;

    // stage Q/K/V/bias-column into smem
    for (int e = tid; e < BH_ELEM; e += 256) {
        int t = e >> 5, d = e & 31;
        Kt[d * NTOK + t] = g_k[base + e];
        Vs[e]            = g_v[base + e];
        Qs[e]            = g_q[base + e];
    }
    for (int e = tid; e < 729; e += 256)
        tab[e] = bias_table[e * HEADS + h];
    __syncthreads();

    const int w = tid >> 5, l = tid & 31;
    float* Pw = Pb + w * 784;

    for (int g = w; g < 49; g += 8) {
        const int i0 = g * 4;

        // ---- S = Q K^T (4 queries x 7 j-strips of 32) ----
        float a0[7] = {}, a1[7] = {}, a2[7] = {}, a3[7] = {};
        for (int d = 0; d < 32; ++d) {
            float q0 = Qs[(i0 + 0) * 32 + d];
            float q1 = Qs[(i0 + 1) * 32 + d];
            float q2 = Qs[(i0 + 2) * 32 + d];
            float q3 = Qs[(i0 + 3) * 32 + d];
            const float* kd = Kt + d * NTOK;
            #pragma unroll
            for (int m = 0; m < 7; ++m) {
                int j = l + (m << 5);
                float kv = (j < NTOK) ? kd[j] : 0.f;
                a0[m] += q0 * kv;
                a1[m] += q1 * kv;
                a2[m] += q2 * kv;
                a3[m] += q3 * kv;
            }
        }

        // ---- bias + mask ----
        const int yi0 = (i0 + 0) / 14, xi0 = (i0 + 0) - yi0 * 14;
        const int yi1 = (i0 + 1) / 14, xi1 = (i0 + 1) - yi1 * 14;
        const int yi2 = (i0 + 2) / 14, xi2 = (i0 + 2) - yi2 * 14;
        const int yi3 = (i0 + 3) / 14, xi3 = (i0 + 3) - yi3 * 14;

        float s0[7], s1[7], s2[7], s3[7];
        float mx0 = -1e30f, mx1 = -1e30f, mx2 = -1e30f, mx3 = -1e30f;
        #pragma unroll
        for (int m = 0; m < 7; ++m) {
            int j = l + (m << 5);
            if (j < NTOK) {
                int yj = j / 14, xj = j - yj * 14;
                s0[m] = a0[m] + tab[(yi0 - yj + 13) * 27 + (xi0 - xj + 13)];
                s1[m] = a1[m] + tab[(yi1 - yj + 13) * 27 + (xi1 - xj + 13)];
                s2[m] = a2[m] + tab[(yi2 - yj + 13) * 27 + (xi2 - xj + 13)];
                s3[m] = a3[m] + tab[(yi3 - yj + 13) * 27 + (xi3 - xj + 13)];
            } else {
                s0[m] = s1[m] = s2[m] = s3[m] = -1e30f;
            }
            mx0 = fmaxf(mx0, s0[m]); mx1 = fmaxf(mx1, s1[m]);
            mx2 = fmaxf(mx2, s2[m]); mx3 = fmaxf(mx3, s3[m]);
        }

        // ---- softmax (warp reductions) ----
        #pragma unroll
        for (int off = 16; off; off >>= 1) {
            mx0 = fmaxf(mx0, __shfl_xor_sync(0xffffffffu, mx0, off));
            mx1 = fmaxf(mx1, __shfl_xor_sync(0xffffffffu, mx1, off));
            mx2 = fmaxf(mx2, __shfl_xor_sync(0xffffffffu, mx2, off));
            mx3 = fmaxf(mx3, __shfl_xor_sync(0xffffffffu, mx3, off));
        }
        float sum0 = 0.f, sum1 = 0.f, sum2 = 0.f, sum3 = 0.f;
        #pragma unroll
        for (int m = 0; m < 7; ++m) {
            s0[m] = __expf(s0[m] - mx0); sum0 += s0[m];
            s1[m] = __expf(s1[m] - mx1); sum1 += s1[m];
            s2[m] = __expf(s2[m] - mx2); sum2 += s2[m];
            s3[m] = __expf(s3[m] - mx3); sum3 += s3[m];
        }
        #pragma unroll
        for (int off = 16; off; off >>= 1) {
            sum0 += __shfl_xor_sync(0xffffffffu, sum0, off);
            sum1 += __shfl_xor_sync(0xffffffffu, sum1, off);
            sum2 += __shfl_xor_sync(0xffffffffu, sum2, off);
            sum3 += __shfl_xor_sync(0xffffffffu, sum3, off);
        }
        const float inv0 = 1.f / sum0, inv1 = 1.f / sum1;
        const float inv2 = 1.f / sum2, inv3 = 1.f / sum3;

        // stage P interleaved x4 (float4 per store -> conflict-free STS.128)
        #pragma unroll
        for (int m = 0; m < 7; ++m) {
            int j = l + (m << 5);
            if (j < NTOK) {
                float4 p = make_float4(s0[m] * inv0, s1[m] * inv1,
                                       s2[m] * inv2, s3[m] * inv3);
                *(float4*)&Pw[j << 2] = p;
            }
        }
        __syncwarp();

        // ---- O = P V : lane = head dim, float4 broadcast of P ----
        float o0 = 0.f, o1 = 0.f, o2 = 0.f, o3 = 0.f;
        #pragma unroll 4
        for (int j = 0; j < NTOK; ++j) {
            float4 p = *(const float4*)&Pw[j << 2];
            float vv = Vs[(j << 5) + l];
            o0 += p.x * vv; o1 += p.y * vv; o2 += p.z * vv; o3 += p.w * vv;
        }

        size_t ob = ((size_t)b * NTOK + i0) * CDIM + h * HD + l;
        g_ao[ob]              = o0;
        g_ao[ob + CDIM]       = o1;
        g_ao[ob + 2 * CDIM]   = o2;
        g_ao[ob + 3 * CDIM]   = o3;
        __syncwarp();
    }
}

// =====================================================================================
// Kernel 3: proj GEMM + bias.  out[25088,512] = AO[25088,512] @ Wp[512,512] + bias
// =====================================================================================
__global__ __launch_bounds__(256)
void proj_gemm_kernel(const float* __restrict__ W, const float* __restrict__ bias,
                      float* __restrict__ out)
{
    __shared__ float As[8][128];
    __shared__ float Bs[8][128];

    const int tid = threadIdx.x;
    const int bm = blockIdx.y, bn = blockIdx.x;

    const int arow = tid >> 1;
    const int acol = (tid & 1) << 2;
    const int brow = tid >> 5;
    const int bcol = (tid & 31) << 2;

    const float* Ap = g_ao + (size_t)(bm * 128 + arow) * CDIM + acol;
    const float* Bp = W + (size_t)brow * CDIM + bn * 128 + bcol;

    float4 aR = *(const float4*)Ap;
    float4 bR = *(const float4*)Bp;

    float acc[8][8] = {};
    const int tx = tid & 15, ty = tid >> 4;

    for (int kt = 0; kt < CDIM / 8; ++kt) {
        As[acol + 0][arow] = aR.x;
        As[acol + 1][arow] = aR.y;
        As[acol + 2][arow] = aR.z;
        As[acol + 3][arow] = aR.w;
        *(float4*)&Bs[brow][bcol] = bR;
        __syncthreads();

        if (kt < CDIM / 8 - 1) {
            aR = *(const float4*)(Ap + (kt + 1) * 8);
            bR = *(const float4*)(Bp + (size_t)(kt + 1) * 8 * CDIM);
        }

        #pragma unroll
        for (int kk = 0; kk < 8; ++kk) {
            float a[8], b[8];
            *(float4*)&a[0] = *(const float4*)&As[kk][ty * 8];
            *(float4*)&a[4] = *(const float4*)&As[kk][ty * 8 + 4];
            *(float4*)&b[0] = *(const float4*)&Bs[kk][tx * 8];
            *(float4*)&b[4] = *(const float4*)&Bs[kk][tx * 8 + 4];
            #pragma unroll
            for (int i = 0; i < 8; ++i)
                #pragma unroll
                for (int j = 0; j < 8; ++j)
                    acc[i][j] += a[i] * b[j];
        }
        __syncthreads();
    }

    #pragma unroll
    for (int i = 0; i < 8; ++i) {
        int row = bm * 128 + ty * 8 + i;
        #pragma unroll
        for (int j = 0; j < 8; ++j) {
            int col = bn * 128 + tx * 8 + j;
            out[(size_t)row * CDIM + col] = acc[i][j] + bias[col];
        }
    }
}

// =====================================================================================
// launch
// =====================================================================================
extern "C" void kernel_launch(void* const* d_in, const int* in_sizes, int n_in,
                              void* d_out, int out_size)
{
    const float* x       = (const float*)d_in[0];   // [128,196,512]
    const float* qkv_w   = (const float*)d_in[1];   // [512,1536]
    const float* tableb  = (const float*)d_in[2];   // [729,16]
    const float* proj_w  = (const float*)d_in[3];   // [512,512]
    const float* proj_b  = (const float*)d_in[4];   // [512]
    // d_in[5] = rel_pos_index: intentionally unused (recomputed arithmetically,
    // dtype-agnostic).
    float* out = (float*)d_out;                      // [128,196,512] f32

    const int ATTN_SMEM = 25824 * (int)sizeof(float);   // 103,296 B
    cudaFuncSetAttribute(attn_kernel,
                         cudaFuncAttributeMaxDynamicSharedMemorySize, ATTN_SMEM);

    dim3 g1(NQKV / 128, MROWS / 128);   // (12, 196)
    qkv_gemm_kernel<<<g1, 256>>>(x, qkv_w);

    attn_kernel<<<BATCH * HEADS, 256, ATTN_SMEM>>>(tableb);

    dim3 g3(CDIM / 128, MROWS / 128);   // (4, 196)
    proj_gemm_kernel<<<g3, 256>>>(proj_w, proj_b, out);
}